// round 16
// baseline (speedup 1.0000x reference)
#include <cuda_runtime.h>
#include <math.h>
#include <stdint.h>

#define BB 16384

__device__ __align__(16) float g_mempre[(size_t)BB * 4096];   // 256 MB
// pre-chunked weights (filled by prep_k each call)
__device__ __align__(16) float g_wc[524288];                  // Wc0   2 MB
__device__ __align__(16) float g_wm[524288];                  // Wm1   2 MB
__device__ __align__(16) float g_ws[786432];                  // Wsig  3 MB
__device__ __align__(16) float g_wez[16384];                  // [We|Wz], k-split NB=128 chunks
__device__ __align__(16) float g_wza[4096];                   // Wza, full NB=64 chunk

__device__ __forceinline__ float sigmoidf_(float x) { return 1.0f / (1.0f + __expf(-x)); }

__device__ __forceinline__ uint32_t smem_u32(const void* p) {
    uint32_t a;
    asm("{ .reg .u64 t; cvta.to.shared.u64 t, %1; cvt.u32.u64 %0, t; }" : "=r"(a) : "l"(p));
    return a;
}
__device__ __forceinline__ void ldsm4(uint32_t* d, uint32_t addr) {
    asm volatile("ldmatrix.sync.aligned.m8n8.x4.shared.b16 {%0,%1,%2,%3}, [%4];"
        : "=r"(d[0]), "=r"(d[1]), "=r"(d[2]), "=r"(d[3]) : "r"(addr));
}
__device__ __forceinline__ void mma8(float* c, const uint32_t* a, uint32_t b0, uint32_t b1) {
    asm volatile("mma.sync.aligned.m16n8k8.row.col.f32.tf32.tf32.f32 "
        "{%0,%1,%2,%3}, {%4,%5,%6,%7}, {%8,%9}, {%0,%1,%2,%3};"
        : "+f"(c[0]), "+f"(c[1]), "+f"(c[2]), "+f"(c[3])
        : "r"(a[0]), "r"(a[1]), "r"(a[2]), "r"(a[3]), "r"(b0), "r"(b1));
}
__device__ __forceinline__ void cp16(uint32_t dst, const void* src) {
    asm volatile("cp.async.cg.shared.global [%0], [%1], 16;" :: "r"(dst), "l"(src));
}
__device__ __forceinline__ void cp_commit() {
    asm volatile("cp.async.commit_group;" ::: "memory");
}
template <int N>
__device__ __forceinline__ void cp_wait() {
    asm volatile("cp.async.wait_group %0;" :: "n"(N) : "memory");
}
// B-operand x4: one k8 step, two n8 tiles (pair p)
__device__ __forceinline__ uint32_t boff4(int NB, int wn, int NW, int p, int lane) {
    return (uint32_t)(((((lane >> 3) & 1) * NB) + wn * NW + p * 16 +
                      (lane & 7) + ((lane >> 4) << 3)) * 16);
}
// swizzled mempre chunk address (128-row tiles)
__device__ __forceinline__ uint32_t r1a(int kb, int row) {
    return (uint32_t)((kb * 128 + (row ^ (kb & 7))) * 16);
}

// ---- SMEM map (bytes) ----
// [0,65536)        c0 chunks; later e1 @0 (32K), z1/add @32768 (32K)
// [65536,98304)    MP: mempre chunk (32K, swizzled)
// [98304,131072)   WM: Wm1 slice (32K, single)
// [131072,229376)  WS: 2 x 48K Wsig buffers
// P1:  3 x 32768 stages @65536..163840; epi stage 128x132 @65536
// P4a: siga 96K @65536 | EZ B 32K @163840
// P4b: zt chunk 32K @163840 | Wza 16K @196608 | mkt @196608 (after Wza) | sww 32K @163840
#define C0_OFF 0
#define MP_OFF 65536
#define WM_OFF 98304
#define WS_OFF 131072
#define ST_OFF 81920
#define SMEM_TOTAL 229376

// ============ prep: rewrite weights into SMEM chunk layout ============
__global__ void __launch_bounds__(512) prep_k(
    const float* __restrict__ Wc0, const float* __restrict__ Wm1,
    const float* __restrict__ Wemv, const float* __restrict__ Wzmv,
    const float* __restrict__ Wamv, const float* __restrict__ We,
    const float* __restrict__ Wz,  const float* __restrict__ Wza)
{
    int i = blockIdx.x * 512 + threadIdx.x;
    if (i < 524288) {                       // Wc0: per 32-k chunk c
        int c = i >> 12, rem = i & 4095;
        int q = rem >> 9, t = rem & 511, n = t >> 2, r = t & 3;
        int k = c * 32 + q * 4 + r;
        g_wc[i] = Wc0[(size_t)k * 128 + n];
    } else if (i < 1048576) {               // Wm1: per 64-col slice o, 128k x 64n
        int j = i - 524288;
        int o = j >> 13, rem = j & 8191;
        int q = rem >> 8, t = rem & 255, n = t >> 2, r = t & 3;
        int k = q * 4 + r;
        g_wm[j] = Wm1[(size_t)k * 4096 + o * 64 + n];
    } else if (i < 1835008) {               // Wsig: per (o,h) 32k x 192n
        int j = i - 1048576;
        int oh = j / 6144, rem = j - oh * 6144;
        int q = rem / 768, t = rem - q * 768, n = t >> 2, r = t & 3;
        int k = oh * 32 + q * 4 + r;
        const float* W = (n < 64) ? Wemv : (n < 128) ? Wzmv : Wamv;
        g_ws[j] = W[(size_t)k * 64 + (n & 63)];
    } else if (i < 1851392) {               // [We|Wz] k-split: half h, 64k x 128n chunk
        int j = i - 1835008;
        int h = j >> 13, jj = j & 8191;
        int q = jj >> 9, t = jj & 511, n = t >> 2, r = t & 3;
        int k = h * 64 + q * 4 + r;
        g_wez[j] = (n < 64) ? We[(size_t)k * 64 + n] : Wz[(size_t)k * 64 + (n - 64)];
    } else if (i < 1855488) {               // Wza full: 64k x 64n chunk
        int j = i - 1851392;
        int q = j >> 8, t = j & 255, n = t >> 2, r = t & 3;
        int k = q * 4 + r;
        g_wza[j] = Wza[(size_t)k * 64 + n];
    }
}

// ====================== fused row-block kernel ======================
__global__ void __launch_bounds__(512, 1) fused_k(
    const float* __restrict__ ck,  const float* __restrict__ mk,
    const float* __restrict__ qa,  const float* __restrict__ mv,
    const float* __restrict__ be,  const float* __restrict__ bemv,
    const float* __restrict__ bza, const float* __restrict__ bamv,
    const float* __restrict__ bc0, const float* __restrict__ bm1,
    const float* __restrict__ bz,  const float* __restrict__ bzmv,
    float* __restrict__ outp)
{
    extern __shared__ char smem[];
    const int tid  = threadIdx.x;
    const int lane = tid & 31;
    const int wid  = tid >> 5;
    const int wm   = wid & 3;
    const int wn   = wid >> 2;
    const int m0   = blockIdx.x * 128;

    uint32_t sb  = smem_u32(smem);
    uint32_t c0b = sb;

    const uint32_t aoff0 = (uint32_t)((((lane >> 4) * 128) + wm * 32 + (lane & 15)) * 16);
    const uint32_t aoff1 = aoff0 + 256;
    const uint32_t gbo   = boff4(64, wn, 16, 0, lane);
    const int frow0 = wm * 32 + (lane >> 2);
    const int fc2   = 2 * (lane & 3);

    // ============ P1: c0 = qa * sigmoid(mv @ Wc0 + bc0), 3-stage pipeline ============
    {
        float cacc[2][4][4];
#pragma unroll
        for (int mt = 0; mt < 2; mt++)
#pragma unroll
            for (int nt = 0; nt < 4; nt++)
#pragma unroll
                for (int j = 0; j < 4; j++) cacc[mt][nt][j] = 0.f;

        auto issue1 = [&](int c) {
            uint32_t ab = sb + 65536 + (c % 3) * 32768, bb2 = ab + 16384;
            int kt = c * 32;
#pragma unroll
            for (int i = 0; i < 2; i++) {
                int v = tid + i * 512;
                int kq = v & 7, r = v >> 3;
                cp16(ab + (kq * 128 + r) * 16, &mv[(size_t)(m0 + r) * 4096 + kt + kq * 4]);
            }
#pragma unroll
            for (int i = 0; i < 2; i++) {              // Wc0 pre-chunked: linear cp16
                int v = tid + i * 512;
                cp16(bb2 + v * 16, &g_wc[(size_t)c * 4096 + (size_t)v * 4]);
            }
            cp_commit();
        };
        issue1(0); issue1(1);
#pragma unroll 1
        for (int c = 0; c < 128; c++) {
            if (c == 127) cp_wait<0>(); else cp_wait<1>();
            __syncthreads();
            if (c + 2 < 128) issue1(c + 2);
            uint32_t ab = sb + 65536 + (c % 3) * 32768, bb2 = ab + 16384;
#pragma unroll
            for (int s = 0; s < 4; s++) {
                uint32_t a0[4], a1[4];
                ldsm4(a0, ab + aoff0 + s * 4096);
                ldsm4(a1, ab + aoff1 + s * 4096);
#pragma unroll
                for (int p = 0; p < 2; p++) {
                    uint32_t b[4];
                    ldsm4(b, bb2 + boff4(128, wn, 32, p, lane) + s * 4096);
                    mma8(cacc[0][2 * p],     a0, b[0], b[1]);
                    mma8(cacc[0][2 * p + 1], a0, b[2], b[3]);
                    mma8(cacc[1][2 * p],     a1, b[0], b[1]);
                    mma8(cacc[1][2 * p + 1], a1, b[2], b[3]);
                }
            }
        }
        __syncthreads();
        float* stg = (float*)(smem + 65536);
#pragma unroll
        for (int mt = 0; mt < 2; mt++)
#pragma unroll
            for (int nt = 0; nt < 4; nt++) {
                int row = frow0 + mt * 16;
                int col = wn * 32 + nt * 8 + fc2;
                *(float2*)&stg[row * 132 + col]       = make_float2(cacc[mt][nt][0], cacc[mt][nt][1]);
                *(float2*)&stg[(row + 8) * 132 + col] = make_float2(cacc[mt][nt][2], cacc[mt][nt][3]);
            }
        __syncthreads();
#pragma unroll
        for (int i = 0; i < 32; i++) {
            int v = tid + i * 512;
            int row = v >> 7, k = v & 127;
            float c0v = __ldg(&qa[(size_t)(m0 + row) * 128 + k]) *
                        sigmoidf_(stg[row * 132 + k] + __ldg(&bc0[k]));
            *(float*)(smem + C0_OFF + ((k >> 2) * 128 + row) * 16 + (k & 3) * 4) = c0v;
        }
        __syncthreads();
    }

    // ============ P3: per 64-col block; ws prefetched a full iteration ahead ============
    float sacc[2][6][4];
#pragma unroll
    for (int mt = 0; mt < 2; mt++)
#pragma unroll
        for (int nt = 0; nt < 6; nt++)
#pragma unroll
            for (int j = 0; j < 4; j++) sacc[mt][nt][j] = 0.f;
    {
        auto load_ws = [&](int o) {                    // 48K Wsig(o) -> WS[o&1]
            uint32_t dst = sb + WS_OFF + (uint32_t)(o & 1) * 49152;
#pragma unroll
            for (int i = 0; i < 6; i++) {
                int v = tid + i * 512;
                cp16(dst + v * 16, &g_ws[(size_t)o * 12288 + (size_t)v * 4]);
            }
            cp_commit();
        };
        auto load_wm = [&](int o) {                    // 32K Wm1 slice -> WM (single)
#pragma unroll
            for (int i = 0; i < 4; i++) {
                int v = tid + i * 512;
                cp16(sb + WM_OFF + v * 16, &g_wm[(size_t)o * 8192 + (size_t)v * 4]);
            }
            cp_commit();
        };

        load_ws(0);
        load_wm(0);

#pragma unroll 1
        for (int o = 0; o < 64; o++) {
            cp_wait<0>();
            __syncthreads();                           // ws(o), wm(o) visible; MP & WS[(o+1)&1] free
            if (o < 63) load_ws(o + 1);                // full-iteration cover

            // gate mma: A = c0 (K=128), B = WM (NB=64)
            float gacc[2][2][4];
#pragma unroll
            for (int mt = 0; mt < 2; mt++)
#pragma unroll
                for (int nt = 0; nt < 2; nt++)
#pragma unroll
                    for (int j = 0; j < 4; j++) gacc[mt][nt][j] = 0.f;
#pragma unroll
            for (int s = 0; s < 16; s++) {
                uint32_t a0[4], a1[4], b[4];
                ldsm4(a0, c0b + aoff0 + s * 4096);
                ldsm4(a1, c0b + aoff1 + s * 4096);
                ldsm4(b, sb + WM_OFF + gbo + s * 2048);
                mma8(gacc[0][0], a0, b[0], b[1]);
                mma8(gacc[0][1], a0, b[2], b[3]);
                mma8(gacc[1][0], a1, b[0], b[1]);
                mma8(gacc[1][1], a1, b[2], b[3]);
            }
            // epilogue: mempre = mv(LDG) * sigmoid(gate + bm1) -> MP chunk + gmem
            const int kt = o * 64;
#pragma unroll
            for (int mt = 0; mt < 2; mt++)
#pragma unroll
                for (int nt = 0; nt < 2; nt++) {
                    int colb = wn * 16 + nt * 8 + fc2;
                    float b0v = __ldg(&bm1[kt + colb]);
                    float b1v = __ldg(&bm1[kt + colb + 1]);
                    int kb = colb >> 2, w0 = colb & 3;
#pragma unroll
                    for (int half = 0; half < 2; half++) {
                        int row = frow0 + mt * 16 + half * 8;
                        float2 mvv = *(const float2*)&mv[(size_t)(m0 + row) * 4096 + kt + colb];
                        float p0 = mvv.x * sigmoidf_(gacc[mt][nt][half * 2 + 0] + b0v);
                        float p1 = mvv.y * sigmoidf_(gacc[mt][nt][half * 2 + 1] + b1v);
                        uint32_t off = (uint32_t)MP_OFF + r1a(kb, row) + w0 * 4;
                        *(float*)(smem + off)     = p0;
                        *(float*)(smem + off + 4) = p1;
                        *(float2*)&g_mempre[(size_t)(m0 + row) * 4096 + kt + colb] =
                            make_float2(p0, p1);
                    }
                }
            __syncthreads();                           // MP visible; WM free
            if (o < 63) load_wm(o + 1);                // cover = SIG burst + next wait

            // SIG mma: A = MP (K=64, swizzled), B = WS[o&1] (NB=192)
            uint32_t wsb = sb + WS_OFF + (uint32_t)(o & 1) * 49152;
#pragma unroll
            for (int h = 0; h < 2; h++) {
                uint32_t bbuf = wsb + h * 24576;
#pragma unroll
                for (int s = 0; s < 4; s++) {
                    int kb = 2 * (h * 4 + s) + (lane >> 4);
                    uint32_t ax = sb + MP_OFF +
                        (uint32_t)((kb * 128 + ((wm * 32 + (lane & 15)) ^ (kb & 7))) * 16);
                    uint32_t a0[4], a1[4];
                    ldsm4(a0, ax);
                    ldsm4(a1, ax + 256);
#pragma unroll
                    for (int p = 0; p < 3; p++) {
                        uint32_t b[4];
                        ldsm4(b, bbuf + boff4(192, wn, 48, p, lane) + s * 6144);
                        mma8(sacc[0][2 * p],     a0, b[0], b[1]);
                        mma8(sacc[0][2 * p + 1], a0, b[2], b[3]);
                        mma8(sacc[1][2 * p],     a1, b[0], b[1]);
                        mma8(sacc[1][2 * p + 1], a1, b[2], b[3]);
                    }
                }
            }
        }
    }

    // ============ P4a: sacc dump -> siga; EZ = c0 @ [We|Wz], k-split NB=128 ============
    __syncthreads();
    {
        auto issue_ez = [&](int h) {
#pragma unroll
            for (int i = 0; i < 4; i++) {              // 32KB linear
                int v = tid + i * 512;
                cp16(sb + 163840 + v * 16, &g_wez[(size_t)h * 8192 + (size_t)v * 4]);
            }
            cp_commit();
        };
        issue_ez(0);
        float* siga = (float*)(smem + 65536);
#pragma unroll
        for (int mt = 0; mt < 2; mt++)
#pragma unroll
            for (int nt = 0; nt < 6; nt++)
#pragma unroll
                for (int idx = 0; idx < 4; idx++) {
                    int row = frow0 + mt * 16 + (idx >> 1) * 8;
                    int col = wn * 48 + nt * 8 + fc2 + (idx & 1);
                    float bv = (col < 64) ? __ldg(&bemv[col])
                             : (col < 128) ? __ldg(&bzmv[col - 64])
                                           : __ldg(&bamv[col - 128]);
                    siga[row * 192 + col] = sacc[mt][nt][idx] + bv;
                }
        cp_wait<0>(); __syncthreads();

        float ez[2][4][4];
#pragma unroll
        for (int mt = 0; mt < 2; mt++)
#pragma unroll
            for (int nt = 0; nt < 4; nt++)
#pragma unroll
                for (int j = 0; j < 4; j++) ez[mt][nt][j] = 0.f;
#pragma unroll
        for (int s = 0; s < 8; s++) {                  // k-half 0
            uint32_t a0[4], a1[4];
            ldsm4(a0, c0b + aoff0 + s * 4096);
            ldsm4(a1, c0b + aoff1 + s * 4096);
#pragma unroll
            for (int p = 0; p < 2; p++) {
                uint32_t b[4];
                ldsm4(b, sb + 163840 + boff4(128, wn, 32, p, lane) + s * 4096);
                mma8(ez[0][2 * p],     a0, b[0], b[1]);
                mma8(ez[0][2 * p + 1], a0, b[2], b[3]);
                mma8(ez[1][2 * p],     a1, b[0], b[1]);
                mma8(ez[1][2 * p + 1], a1, b[2], b[3]);
            }
        }
        __syncthreads();
        issue_ez(1);
        cp_wait<0>(); __syncthreads();
#pragma unroll
        for (int s = 0; s < 8; s++) {                  // k-half 1
            uint32_t a0[4], a1[4];
            ldsm4(a0, c0b + aoff0 + (8 + s) * 4096);
            ldsm4(a1, c0b + aoff1 + (8 + s) * 4096);
#pragma unroll
            for (int p = 0; p < 2; p++) {
                uint32_t b[4];
                ldsm4(b, sb + 163840 + boff4(128, wn, 32, p, lane) + s * 4096);
                mma8(ez[0][2 * p],     a0, b[0], b[1]);
                mma8(ez[0][2 * p + 1], a0, b[2], b[3]);
                mma8(ez[1][2 * p],     a1, b[0], b[1]);
                mma8(ez[1][2 * p + 1], a1, b[2], b[3]);
            }
        }
        __syncthreads();  // c0 reads complete before overwrite
        float* e1a = (float*)smem;
        float* z1a = (float*)(smem + 32768);
#pragma unroll
        for (int mt = 0; mt < 2; mt++)
#pragma unroll
            for (int nt = 0; nt < 4; nt++)
#pragma unroll
                for (int idx = 0; idx < 4; idx++) {
                    int row = frow0 + mt * 16 + (idx >> 1) * 8;
                    int col = wn * 32 + nt * 8 + fc2 + (idx & 1);
                    float v = ez[mt][nt][idx];
                    if (col < 64) e1a[row * 64 + col] = sigmoidf_(v + __ldg(&be[col]));
                    else          z1a[row * 64 + (col - 64)] = v + __ldg(&bz[col - 64]);
                }
        __syncthreads();
    }

    // ============ P4b: zt, erase, add (single pass) + own-block softmax ============
    {
        float* e1a  = (float*)smem;
        float* z1a  = (float*)(smem + 32768);
        float* siga = (float*)(smem + 65536);

        // Wza full B (16KB) at 196608
#pragma unroll
        for (int i = 0; i < 2; i++) {
            int v = tid + i * 512;
            cp16(sb + 196608 + v * 16, &g_wza[(size_t)v * 4]);
        }
        cp_commit();
        // zt full chunk at 163840; erase in place
#pragma unroll
        for (int i = 0; i < 16; i++) {
            int v = tid + i * 512;
            int row = v >> 6, j = v & 63;
            float ztv = sigmoidf_(z1a[row * 64 + j] + siga[row * 192 + 64 + j]);
            *(float*)(smem + 163840 + ((j >> 2) * 128 + row) * 16 + (j & 3) * 4) = ztv;
            e1a[row * 64 + j] = sigmoidf_(e1a[row * 64 + j] + sigmoidf_(siga[row * 192 + j]));
        }
        cp_wait<0>(); __syncthreads();

        float zaacc[2][2][4];
#pragma unroll
        for (int mt = 0; mt < 2; mt++)
#pragma unroll
            for (int nt = 0; nt < 2; nt++)
#pragma unroll
                for (int j = 0; j < 4; j++) zaacc[mt][nt][j] = 0.f;
#pragma unroll
        for (int s = 0; s < 8; s++) {
            uint32_t a0[4], a1[4], b[4];
            ldsm4(a0, sb + 163840 + aoff0 + s * 4096);
            ldsm4(a1, sb + 163840 + aoff1 + s * 4096);
            ldsm4(b, sb + 196608 + gbo + s * 2048);
            mma8(zaacc[0][0], a0, b[0], b[1]);
            mma8(zaacc[0][1], a0, b[2], b[3]);
            mma8(zaacc[1][0], a1, b[0], b[1]);
            mma8(zaacc[1][1], a1, b[2], b[3]);
        }
        __syncthreads();   // zt/Wza reads done (regions reused below)

        // add -> z1a
#pragma unroll
        for (int mt = 0; mt < 2; mt++)
#pragma unroll
            for (int nt = 0; nt < 2; nt++)
#pragma unroll
                for (int idx = 0; idx < 4; idx++) {
                    int row = frow0 + mt * 16 + (idx >> 1) * 8;
                    int col = wn * 16 + nt * 8 + fc2 + (idx & 1);
                    z1a[row * 64 + col] =
                        tanhf(tanhf(zaacc[mt][nt][idx] + __ldg(&bza[col])) +
                              tanhf(siga[row * 192 + 128 + col]));
                }
        // mk transposed (padded 65) -> 196608 (Wza dead)
        float* mkt = (float*)(smem + 196608);
#pragma unroll
        for (int i = 0; i < 8; i++) {
            int v = tid + i * 512;
            int t_ = v >> 6, k = v & 63;
            mkt[k * 65 + t_] = __ldg(&mk[v]);
        }
        __syncthreads();   // add + mkt visible

        // ww softmax for this block's 128 rows -> sww at 163840 (zt dead)
        {
            float* sww = (float*)(smem + 163840);
            int row = tid >> 2, sub = tid & 3;
            size_t gr = (size_t)(m0 + row);
            float dots[16];
#pragma unroll
            for (int jj = 0; jj < 16; jj++) dots[jj] = 0.f;
#pragma unroll 4
            for (int k = 0; k < 64; k++) {
                float cv = __ldg(&ck[gr * 64 + k]);
                const float* mp_ = &mkt[k * 65 + sub * 16];
#pragma unroll
                for (int jj = 0; jj < 16; jj++) dots[jj] = fmaf(cv, mp_[jj], dots[jj]);
            }
            float mx = dots[0];
#pragma unroll
            for (int jj = 1; jj < 16; jj++) mx = fmaxf(mx, dots[jj]);
            mx = fmaxf(mx, __shfl_xor_sync(0xffffffffu, mx, 1));
            mx = fmaxf(mx, __shfl_xor_sync(0xffffffffu, mx, 2));
            float sum = 0.f;
#pragma unroll
            for (int jj = 0; jj < 16; jj++) { dots[jj] = __expf(dots[jj] - mx); sum += dots[jj]; }
            sum += __shfl_xor_sync(0xffffffffu, sum, 1);
            sum += __shfl_xor_sync(0xffffffffu, sum, 2);
            float inv = 1.f / sum;
#pragma unroll
            for (int jj = 0; jj < 16; jj++)
                sww[row * 64 + sub * 16 + jj] = dots[jj] * inv;
        }
        __syncthreads();
    }

    // ============ P5: out = mempre*(1 - w*erase) + w*add ============
    {
        const float* er = (const float*)smem;
        const float* ad = (const float*)(smem + 32768);
        const float* sw = (const float*)(smem + 163840);
#pragma unroll 4
        for (int it = 0; it < 256; it++) {
            int v = tid + it * 512;
            int row = v >> 10, q = v & 1023;
            float4 mp = *(const float4*)&g_mempre[(size_t)(m0 + row) * 4096 + q * 4];
            float w = sw[row * 64 + (q >> 4)];
            float4 e4 = *(const float4*)&er[row * 64 + (q & 15) * 4];
            float4 a4 = *(const float4*)&ad[row * 64 + (q & 15) * 4];
            float4 r;
            r.x = mp.x * (1.f - w * e4.x) + w * a4.x;
            r.y = mp.y * (1.f - w * e4.y) + w * a4.y;
            r.z = mp.z * (1.f - w * e4.z) + w * a4.z;
            r.w = mp.w * (1.f - w * e4.w) + w * a4.w;
            *(float4*)&outp[(size_t)(m0 + row) * 4096 + q * 4] = r;
        }
    }
}

// ====================== launch ======================
extern "C" void kernel_launch(void* const* d_in, const int* in_sizes, int n_in,
                              void* d_out, int out_size)
{
    const float* control_key  = (const float*)d_in[0];
    const float* control_qa   = (const float*)d_in[1];
    const float* memory_key   = (const float*)d_in[2];
    const float* memory_value = (const float*)d_in[3];
    const float* We   = (const float*)d_in[4];
    const float* be   = (const float*)d_in[5];
    const float* Wemv = (const float*)d_in[6];
    const float* bemv = (const float*)d_in[7];
    const float* Wza  = (const float*)d_in[8];
    const float* bza  = (const float*)d_in[9];
    const float* Wamv = (const float*)d_in[10];
    const float* bamv = (const float*)d_in[11];
    const float* Wc0  = (const float*)d_in[12];
    const float* bc0  = (const float*)d_in[13];
    const float* Wm1  = (const float*)d_in[14];
    const float* bm1  = (const float*)d_in[15];
    const float* Wz   = (const float*)d_in[16];
    const float* bz   = (const float*)d_in[17];
    const float* Wzmv = (const float*)d_in[18];
    const float* bzmv = (const float*)d_in[19];
    float* out = (float*)d_out;

    cudaFuncSetAttribute(fused_k, cudaFuncAttributeMaxDynamicSharedMemorySize, SMEM_TOTAL);

    // pre-chunk weights (3624 blocks cover 1855488 elements)
    prep_k<<<3624, 512>>>(Wc0, Wm1, Wemv, Wzmv, Wamv, We, Wz, Wza);

    fused_k<<<BB / 128, 512, SMEM_TOTAL>>>(
        control_key, memory_key,
        control_qa, memory_value,
        be, bemv, bza, bamv, bc0, bm1, bz, bzmv,
        out);
}

// round 17
// speedup vs baseline: 1.0912x; 1.0912x over previous
#include <cuda_runtime.h>
#include <math.h>
#include <stdint.h>

#define BB 16384

__device__ __align__(16) float g_mempre[(size_t)BB * 4096];   // 256 MB
// pre-chunked weights (filled by prep_k each call)
__device__ __align__(16) float g_wc[524288];                  // Wc0   2 MB
__device__ __align__(16) float g_wm[524288];                  // Wm1   2 MB
__device__ __align__(16) float g_ws[786432];                  // Wsig  3 MB
__device__ __align__(16) float g_wez[16384];                  // [We|Wz], k-split NB=128 chunks
__device__ __align__(16) float g_wza[4096];                   // Wza, full NB=64 chunk

__device__ __forceinline__ float sigmoidf_(float x) { return 1.0f / (1.0f + __expf(-x)); }

__device__ __forceinline__ uint32_t smem_u32(const void* p) {
    uint32_t a;
    asm("{ .reg .u64 t; cvta.to.shared.u64 t, %1; cvt.u32.u64 %0, t; }" : "=r"(a) : "l"(p));
    return a;
}
__device__ __forceinline__ void ldsm4(uint32_t* d, uint32_t addr) {
    asm volatile("ldmatrix.sync.aligned.m8n8.x4.shared.b16 {%0,%1,%2,%3}, [%4];"
        : "=r"(d[0]), "=r"(d[1]), "=r"(d[2]), "=r"(d[3]) : "r"(addr));
}
__device__ __forceinline__ void mma8(float* c, const uint32_t* a, uint32_t b0, uint32_t b1) {
    asm volatile("mma.sync.aligned.m16n8k8.row.col.f32.tf32.tf32.f32 "
        "{%0,%1,%2,%3}, {%4,%5,%6,%7}, {%8,%9}, {%0,%1,%2,%3};"
        : "+f"(c[0]), "+f"(c[1]), "+f"(c[2]), "+f"(c[3])
        : "r"(a[0]), "r"(a[1]), "r"(a[2]), "r"(a[3]), "r"(b0), "r"(b1));
}
__device__ __forceinline__ void cp16(uint32_t dst, const void* src) {
    asm volatile("cp.async.cg.shared.global [%0], [%1], 16;" :: "r"(dst), "l"(src));
}
__device__ __forceinline__ void cp_commit() {
    asm volatile("cp.async.commit_group;" ::: "memory");
}
template <int N>
__device__ __forceinline__ void cp_wait() {
    asm volatile("cp.async.wait_group %0;" :: "n"(N) : "memory");
}
// B-operand x4: one k8 step, two n8 tiles (pair p)
__device__ __forceinline__ uint32_t boff4(int NB, int wn, int NW, int p, int lane) {
    return (uint32_t)(((((lane >> 3) & 1) * NB) + wn * NW + p * 16 +
                      (lane & 7) + ((lane >> 4) << 3)) * 16);
}
// swizzled mv/mempre chunk address (128-row tiles)
__device__ __forceinline__ uint32_t r1a(int kb, int row) {
    return (uint32_t)((kb * 128 + (row ^ (kb & 7))) * 16);
}

// ---- SMEM map (bytes) — round-15 layout; P1 uses 2 x 64K stages @65536 ----
#define C0_OFF 0
#define SMEM_TOTAL 221184

// ============ prep: rewrite weights into SMEM chunk layout ============
__global__ void __launch_bounds__(512) prep_k(
    const float* __restrict__ Wc0, const float* __restrict__ Wm1,
    const float* __restrict__ Wemv, const float* __restrict__ Wzmv,
    const float* __restrict__ Wamv, const float* __restrict__ We,
    const float* __restrict__ Wz,  const float* __restrict__ Wza)
{
    int i = blockIdx.x * 512 + threadIdx.x;
    if (i < 524288) {                       // Wc0: per 32-k chunk c
        int c = i >> 12, rem = i & 4095;
        int q = rem >> 9, t = rem & 511, n = t >> 2, r = t & 3;
        int k = c * 32 + q * 4 + r;
        g_wc[i] = Wc0[(size_t)k * 128 + n];
    } else if (i < 1048576) {               // Wm1: per 64-col slice o, 128k x 64n
        int j = i - 524288;
        int o = j >> 13, rem = j & 8191;
        int q = rem >> 8, t = rem & 255, n = t >> 2, r = t & 3;
        int k = q * 4 + r;
        g_wm[j] = Wm1[(size_t)k * 4096 + o * 64 + n];
    } else if (i < 1835008) {               // Wsig: per (o,h) 32k x 192n
        int j = i - 1048576;
        int oh = j / 6144, rem = j - oh * 6144;
        int q = rem / 768, t = rem - q * 768, n = t >> 2, r = t & 3;
        int k = oh * 32 + q * 4 + r;
        const float* W = (n < 64) ? Wemv : (n < 128) ? Wzmv : Wamv;
        g_ws[j] = W[(size_t)k * 64 + (n & 63)];
    } else if (i < 1851392) {               // [We|Wz] k-split: half h, 64k x 128n chunk
        int j = i - 1835008;
        int h = j >> 13, jj = j & 8191;
        int q = jj >> 9, t = jj & 511, n = t >> 2, r = t & 3;
        int k = h * 64 + q * 4 + r;
        g_wez[j] = (n < 64) ? We[(size_t)k * 64 + n] : Wz[(size_t)k * 64 + (n - 64)];
    } else if (i < 1855488) {               // Wza full: 64k x 64n chunk
        int j = i - 1851392;
        int q = j >> 8, t = j & 255, n = t >> 2, r = t & 3;
        int k = q * 4 + r;
        g_wza[j] = Wza[(size_t)k * 64 + n];
    }
}

// ====================== fused row-block kernel ======================
__global__ void __launch_bounds__(512, 1) fused_k(
    const float* __restrict__ ck,  const float* __restrict__ mk,
    const float* __restrict__ qa,  const float* __restrict__ mv,
    const float* __restrict__ be,  const float* __restrict__ bemv,
    const float* __restrict__ bza, const float* __restrict__ bamv,
    const float* __restrict__ bc0, const float* __restrict__ bm1,
    const float* __restrict__ bz,  const float* __restrict__ bzmv,
    float* __restrict__ outp)
{
    extern __shared__ char smem[];
    const int tid  = threadIdx.x;
    const int lane = tid & 31;
    const int wid  = tid >> 5;
    const int wm   = wid & 3;
    const int wn   = wid >> 2;
    const int m0   = blockIdx.x * 128;

    uint32_t sb  = smem_u32(smem);
    uint32_t c0b = sb;

    const uint32_t aoff0 = (uint32_t)((((lane >> 4) * 128) + wm * 32 + (lane & 15)) * 16);
    const uint32_t aoff1 = aoff0 + 256;
    const uint32_t gbo   = boff4(64, wn, 16, 0, lane);
    const int frow0 = wm * 32 + (lane >> 2);
    const int fc2   = 2 * (lane & 3);

    // ============ P1: c0 = qa * sigmoid(mv @ Wc0 + bc0), BK=64, 2-stage ============
    {
        float cacc[2][4][4];
#pragma unroll
        for (int mt = 0; mt < 2; mt++)
#pragma unroll
            for (int nt = 0; nt < 4; nt++)
#pragma unroll
                for (int j = 0; j < 4; j++) cacc[mt][nt][j] = 0.f;

        auto issue1 = [&](int c) {
            uint32_t ab = sb + 65536 + (uint32_t)(c & 1) * 65536, bb2 = ab + 32768;
            int kt = c * 64;
#pragma unroll
            for (int i = 0; i < 4; i++) {              // mv: 128r x 64k A-chunk
                int v = tid + i * 512;
                int kq = v & 15, r = v >> 4;
                cp16(ab + (kq * 128 + r) * 16, &mv[(size_t)(m0 + r) * 4096 + kt + kq * 4]);
            }
#pragma unroll
            for (int i = 0; i < 4; i++) {              // Wc0 pre-chunked: linear 32K
                int v = tid + i * 512;
                cp16(bb2 + v * 16, &g_wc[(size_t)c * 8192 + (size_t)v * 4]);
            }
            cp_commit();
        };
        issue1(0);
#pragma unroll 1
        for (int c = 0; c < 64; c++) {
            cp_wait<0>();
            __syncthreads();
            if (c + 1 < 64) issue1(c + 1);
            uint32_t ab = sb + 65536 + (uint32_t)(c & 1) * 65536, bb2 = ab + 32768;
#pragma unroll
            for (int s = 0; s < 8; s++) {
                uint32_t a0[4], a1[4];
                ldsm4(a0, ab + aoff0 + s * 4096);
                ldsm4(a1, ab + aoff1 + s * 4096);
#pragma unroll
                for (int p = 0; p < 2; p++) {
                    uint32_t b[4];
                    ldsm4(b, bb2 + boff4(128, wn, 32, p, lane) + s * 4096);
                    mma8(cacc[0][2 * p],     a0, b[0], b[1]);
                    mma8(cacc[0][2 * p + 1], a0, b[2], b[3]);
                    mma8(cacc[1][2 * p],     a1, b[0], b[1]);
                    mma8(cacc[1][2 * p + 1], a1, b[2], b[3]);
                }
            }
        }
        __syncthreads();
        float* stg = (float*)(smem + 65536);
#pragma unroll
        for (int mt = 0; mt < 2; mt++)
#pragma unroll
            for (int nt = 0; nt < 4; nt++) {
                int row = frow0 + mt * 16;
                int col = wn * 32 + nt * 8 + fc2;
                *(float2*)&stg[row * 132 + col]       = make_float2(cacc[mt][nt][0], cacc[mt][nt][1]);
                *(float2*)&stg[(row + 8) * 132 + col] = make_float2(cacc[mt][nt][2], cacc[mt][nt][3]);
            }
        __syncthreads();
#pragma unroll
        for (int i = 0; i < 32; i++) {
            int v = tid + i * 512;
            int row = v >> 7, k = v & 127;
            float c0v = __ldg(&qa[(size_t)(m0 + row) * 128 + k]) *
                        sigmoidf_(stg[row * 132 + k] + __ldg(&bc0[k]));
            *(float*)(smem + C0_OFF + ((k >> 2) * 128 + row) * 16 + (k & 3) * 4) = c0v;
        }
        __syncthreads();
    }

    // ============ P3: per 64-col block: gate -> mempre(inplace) -> SIG (2 syncs/iter) ============
    float sacc[2][6][4];
#pragma unroll
    for (int mt = 0; mt < 2; mt++)
#pragma unroll
        for (int nt = 0; nt < 6; nt++)
#pragma unroll
            for (int j = 0; j < 4; j++) sacc[mt][nt][j] = 0.f;
    {
        auto issue_mw = [&](int o) {
            uint32_t r1b_ = sb + 65536 + (uint32_t)(o & 1) * 32768;
            int kt = o * 64;
#pragma unroll
            for (int i = 0; i < 4; i++) {              // mv 128x64 (A-chunk, swizzled)
                int v = tid + i * 512;
                int kb = v & 15, row = v >> 4;
                cp16(r1b_ + r1a(kb, row), &mv[(size_t)(m0 + row) * 4096 + kt + kb * 4]);
            }
#pragma unroll
            for (int i = 0; i < 4; i++) {              // Wm1 slice pre-chunked: linear
                int v = tid + i * 512;
                cp16(sb + 131072 + v * 16, &g_wm[(size_t)o * 8192 + (size_t)v * 4]);
            }
            cp_commit();
        };
        auto issue_sub = [&](int o, int h) {
            uint32_t bbuf = sb + 163840 + h * 24576;
            int oh = o * 2 + h;
#pragma unroll
            for (int i = 0; i < 3; i++) {              // Wsig pre-chunked: linear
                int v = tid + i * 512;
                cp16(bbuf + v * 16, &g_ws[(size_t)oh * 6144 + (size_t)v * 4]);
            }
            cp_commit();
        };

        issue_mw(0);
#pragma unroll 1
        for (int o = 0; o < 64; o++) {
            cp_wait<0>();
            __syncthreads();                           // mv/Wm1(o) visible; SIG(o-1) done
            issue_sub(o, 0); issue_sub(o, 1);

            // gate mma: A = c0 (K=128), B = Wm1 slice (NB=64)
            float gacc[2][2][4];
#pragma unroll
            for (int mt = 0; mt < 2; mt++)
#pragma unroll
                for (int nt = 0; nt < 2; nt++)
#pragma unroll
                    for (int j = 0; j < 4; j++) gacc[mt][nt][j] = 0.f;
#pragma unroll
            for (int s = 0; s < 16; s++) {
                uint32_t a0[4], a1[4], b[4];
                ldsm4(a0, c0b + aoff0 + s * 4096);
                ldsm4(a1, c0b + aoff1 + s * 4096);
                ldsm4(b, sb + 131072 + gbo + s * 2048);
                mma8(gacc[0][0], a0, b[0], b[1]);
                mma8(gacc[0][1], a0, b[2], b[3]);
                mma8(gacc[1][0], a1, b[0], b[1]);
                mma8(gacc[1][1], a1, b[2], b[3]);
            }
            // epilogue: mempre = mv * sigmoid(gate + bm1) in place + direct STG
            const int kt = o * 64;
            const int r1o = 65536 + (o & 1) * 32768;
#pragma unroll
            for (int mt = 0; mt < 2; mt++)
#pragma unroll
                for (int nt = 0; nt < 2; nt++) {
                    int colb = wn * 16 + nt * 8 + fc2;
                    float b0v = __ldg(&bm1[kt + colb]);
                    float b1v = __ldg(&bm1[kt + colb + 1]);
                    int kb = colb >> 2, w0 = colb & 3;
#pragma unroll
                    for (int half = 0; half < 2; half++) {
                        int row = frow0 + mt * 16 + half * 8;
                        uint32_t off = r1o + r1a(kb, row) + w0 * 4;
                        float p0 = *(float*)(smem + off) *
                                   sigmoidf_(gacc[mt][nt][half * 2 + 0] + b0v);
                        float p1 = *(float*)(smem + off + 4) *
                                   sigmoidf_(gacc[mt][nt][half * 2 + 1] + b1v);
                        *(float*)(smem + off)     = p0;
                        *(float*)(smem + off + 4) = p1;
                        *(float2*)&g_mempre[(size_t)(m0 + row) * 4096 + kt + colb] =
                            make_float2(p0, p1);
                    }
                }
            cp_wait<0>();                              // subs done
            __syncthreads();                           // subs + mempre visible; WM free
            if (o < 63) issue_mw(o + 1);               // cover = SIG burst

            // SIG mma: A = mempre (K=64, swizzled), B = Wsig (NB=192)
            uint32_t r1b_ = sb + r1o;
#pragma unroll
            for (int h = 0; h < 2; h++) {
                uint32_t bbuf = sb + 163840 + h * 24576;
#pragma unroll
                for (int s = 0; s < 4; s++) {
                    int kb = 2 * (h * 4 + s) + (lane >> 4);
                    uint32_t ax = r1b_ +
                        (uint32_t)((kb * 128 + ((wm * 32 + (lane & 15)) ^ (kb & 7))) * 16);
                    uint32_t a0[4], a1[4];
                    ldsm4(a0, ax);
                    ldsm4(a1, ax + 256);
#pragma unroll
                    for (int p = 0; p < 3; p++) {
                        uint32_t b[4];
                        ldsm4(b, bbuf + boff4(192, wn, 48, p, lane) + s * 6144);
                        mma8(sacc[0][2 * p],     a0, b[0], b[1]);
                        mma8(sacc[0][2 * p + 1], a0, b[2], b[3]);
                        mma8(sacc[1][2 * p],     a1, b[0], b[1]);
                        mma8(sacc[1][2 * p + 1], a1, b[2], b[3]);
                    }
                }
            }
        }
    }

    // ============ P4a: sacc dump -> siga; EZ = c0 @ [We|Wz], k-split NB=128 ============
    __syncthreads();
    {
        auto issue_ez = [&](int h) {
#pragma unroll
            for (int i = 0; i < 4; i++) {              // 32KB linear
                int v = tid + i * 512;
                cp16(sb + 163840 + v * 16, &g_wez[(size_t)h * 8192 + (size_t)v * 4]);
            }
            cp_commit();
        };
        issue_ez(0);
        float* siga = (float*)(smem + 65536);
#pragma unroll
        for (int mt = 0; mt < 2; mt++)
#pragma unroll
            for (int nt = 0; nt < 6; nt++)
#pragma unroll
                for (int idx = 0; idx < 4; idx++) {
                    int row = frow0 + mt * 16 + (idx >> 1) * 8;
                    int col = wn * 48 + nt * 8 + fc2 + (idx & 1);
                    float bv = (col < 64) ? __ldg(&bemv[col])
                             : (col < 128) ? __ldg(&bzmv[col - 64])
                                           : __ldg(&bamv[col - 128]);
                    siga[row * 192 + col] = sacc[mt][nt][idx] + bv;
                }
        cp_wait<0>(); __syncthreads();

        float ez[2][4][4];
#pragma unroll
        for (int mt = 0; mt < 2; mt++)
#pragma unroll
            for (int nt = 0; nt < 4; nt++)
#pragma unroll
                for (int j = 0; j < 4; j++) ez[mt][nt][j] = 0.f;
#pragma unroll
        for (int s = 0; s < 8; s++) {                  // k-half 0
            uint32_t a0[4], a1[4];
            ldsm4(a0, c0b + aoff0 + s * 4096);
            ldsm4(a1, c0b + aoff1 + s * 4096);
#pragma unroll
            for (int p = 0; p < 2; p++) {
                uint32_t b[4];
                ldsm4(b, sb + 163840 + boff4(128, wn, 32, p, lane) + s * 4096);
                mma8(ez[0][2 * p],     a0, b[0], b[1]);
                mma8(ez[0][2 * p + 1], a0, b[2], b[3]);
                mma8(ez[1][2 * p],     a1, b[0], b[1]);
                mma8(ez[1][2 * p + 1], a1, b[2], b[3]);
            }
        }
        __syncthreads();
        issue_ez(1);
        cp_wait<0>(); __syncthreads();
#pragma unroll
        for (int s = 0; s < 8; s++) {                  // k-half 1
            uint32_t a0[4], a1[4];
            ldsm4(a0, c0b + aoff0 + (8 + s) * 4096);
            ldsm4(a1, c0b + aoff1 + (8 + s) * 4096);
#pragma unroll
            for (int p = 0; p < 2; p++) {
                uint32_t b[4];
                ldsm4(b, sb + 163840 + boff4(128, wn, 32, p, lane) + s * 4096);
                mma8(ez[0][2 * p],     a0, b[0], b[1]);
                mma8(ez[0][2 * p + 1], a0, b[2], b[3]);
                mma8(ez[1][2 * p],     a1, b[0], b[1]);
                mma8(ez[1][2 * p + 1], a1, b[2], b[3]);
            }
        }
        __syncthreads();  // c0 reads complete before overwrite
        float* e1a = (float*)smem;
        float* z1a = (float*)(smem + 32768);
#pragma unroll
        for (int mt = 0; mt < 2; mt++)
#pragma unroll
            for (int nt = 0; nt < 4; nt++)
#pragma unroll
                for (int idx = 0; idx < 4; idx++) {
                    int row = frow0 + mt * 16 + (idx >> 1) * 8;
                    int col = wn * 32 + nt * 8 + fc2 + (idx & 1);
                    float v = ez[mt][nt][idx];
                    if (col < 64) e1a[row * 64 + col] = sigmoidf_(v + __ldg(&be[col]));
                    else          z1a[row * 64 + (col - 64)] = v + __ldg(&bz[col - 64]);
                }
        __syncthreads();
    }

    // ============ P4b: zt, erase, add (single pass) + own-block softmax ============
    {
        float* e1a  = (float*)smem;
        float* z1a  = (float*)(smem + 32768);
        float* siga = (float*)(smem + 65536);

        // Wza full B (16KB) at 196608
#pragma unroll
        for (int i = 0; i < 2; i++) {
            int v = tid + i * 512;
            cp16(sb + 196608 + v * 16, &g_wza[(size_t)v * 4]);
        }
        cp_commit();
        // zt full chunk at 163840; erase in place
#pragma unroll
        for (int i = 0; i < 16; i++) {
            int v = tid + i * 512;
            int row = v >> 6, j = v & 63;
            float ztv = sigmoidf_(z1a[row * 64 + j] + siga[row * 192 + 64 + j]);
            *(float*)(smem + 163840 + ((j >> 2) * 128 + row) * 16 + (j & 3) * 4) = ztv;
            e1a[row * 64 + j] = sigmoidf_(e1a[row * 64 + j] + sigmoidf_(siga[row * 192 + j]));
        }
        cp_wait<0>(); __syncthreads();

        float zaacc[2][2][4];
#pragma unroll
        for (int mt = 0; mt < 2; mt++)
#pragma unroll
            for (int nt = 0; nt < 2; nt++)
#pragma unroll
                for (int j = 0; j < 4; j++) zaacc[mt][nt][j] = 0.f;
#pragma unroll
        for (int s = 0; s < 8; s++) {
            uint32_t a0[4], a1[4], b[4];
            ldsm4(a0, sb + 163840 + aoff0 + s * 4096);
            ldsm4(a1, sb + 163840 + aoff1 + s * 4096);
            ldsm4(b, sb + 196608 + gbo + s * 2048);
            mma8(zaacc[0][0], a0, b[0], b[1]);
            mma8(zaacc[0][1], a0, b[2], b[3]);
            mma8(zaacc[1][0], a1, b[0], b[1]);
            mma8(zaacc[1][1], a1, b[2], b[3]);
        }
        __syncthreads();   // zt/Wza reads done (regions reused below)

        // add -> z1a
#pragma unroll
        for (int mt = 0; mt < 2; mt++)
#pragma unroll
            for (int nt = 0; nt < 2; nt++)
#pragma unroll
                for (int idx = 0; idx < 4; idx++) {
                    int row = frow0 + mt * 16 + (idx >> 1) * 8;
                    int col = wn * 16 + nt * 8 + fc2 + (idx & 1);
                    z1a[row * 64 + col] =
                        tanhf(tanhf(zaacc[mt][nt][idx] + __ldg(&bza[col])) +
                              tanhf(siga[row * 192 + 128 + col]));
                }
        // mk transposed (padded 65) -> 196608 (Wza dead)
        float* mkt = (float*)(smem + 196608);
#pragma unroll
        for (int i = 0; i < 8; i++) {
            int v = tid + i * 512;
            int t_ = v >> 6, k = v & 63;
            mkt[k * 65 + t_] = __ldg(&mk[v]);
        }
        __syncthreads();   // add + mkt visible

        // ww softmax for this block's 128 rows -> sww at 163840 (zt dead)
        {
            float* sww = (float*)(smem + 163840);
            int row = tid >> 2, sub = tid & 3;
            size_t gr = (size_t)(m0 + row);
            float dots[16];
#pragma unroll
            for (int jj = 0; jj < 16; jj++) dots[jj] = 0.f;
#pragma unroll 4
            for (int k = 0; k < 64; k++) {
                float cv = __ldg(&ck[gr * 64 + k]);
                const float* mp_ = &mkt[k * 65 + sub * 16];
#pragma unroll
                for (int jj = 0; jj < 16; jj++) dots[jj] = fmaf(cv, mp_[jj], dots[jj]);
            }
            float mx = dots[0];
#pragma unroll
            for (int jj = 1; jj < 16; jj++) mx = fmaxf(mx, dots[jj]);
            mx = fmaxf(mx, __shfl_xor_sync(0xffffffffu, mx, 1));
            mx = fmaxf(mx, __shfl_xor_sync(0xffffffffu, mx, 2));
            float sum = 0.f;
#pragma unroll
            for (int jj = 0; jj < 16; jj++) { dots[jj] = __expf(dots[jj] - mx); sum += dots[jj]; }
            sum += __shfl_xor_sync(0xffffffffu, sum, 1);
            sum += __shfl_xor_sync(0xffffffffu, sum, 2);
            float inv = 1.f / sum;
#pragma unroll
            for (int jj = 0; jj < 16; jj++)
                sww[row * 64 + sub * 16 + jj] = dots[jj] * inv;
        }
        __syncthreads();
    }

    // ============ P5: out = mempre*(1 - w*erase) + w*add ============
    {
        const float* er = (const float*)smem;
        const float* ad = (const float*)(smem + 32768);
        const float* sw = (const float*)(smem + 163840);
#pragma unroll 4
        for (int it = 0; it < 256; it++) {
            int v = tid + it * 512;
            int row = v >> 10, q = v & 1023;
            float4 mp = *(const float4*)&g_mempre[(size_t)(m0 + row) * 4096 + q * 4];
            float w = sw[row * 64 + (q >> 4)];
            float4 e4 = *(const float4*)&er[row * 64 + (q & 15) * 4];
            float4 a4 = *(const float4*)&ad[row * 64 + (q & 15) * 4];
            float4 r;
            r.x = mp.x * (1.f - w * e4.x) + w * a4.x;
            r.y = mp.y * (1.f - w * e4.y) + w * a4.y;
            r.z = mp.z * (1.f - w * e4.z) + w * a4.z;
            r.w = mp.w * (1.f - w * e4.w) + w * a4.w;
            *(float4*)&outp[(size_t)(m0 + row) * 4096 + q * 4] = r;
        }
    }
}

// ====================== launch ======================
extern "C" void kernel_launch(void* const* d_in, const int* in_sizes, int n_in,
                              void* d_out, int out_size)
{
    const float* control_key  = (const float*)d_in[0];
    const float* control_qa   = (const float*)d_in[1];
    const float* memory_key   = (const float*)d_in[2];
    const float* memory_value = (const float*)d_in[3];
    const float* We   = (const float*)d_in[4];
    const float* be   = (const float*)d_in[5];
    const float* Wemv = (const float*)d_in[6];
    const float* bemv = (const float*)d_in[7];
    const float* Wza  = (const float*)d_in[8];
    const float* bza  = (const float*)d_in[9];
    const float* Wamv = (const float*)d_in[10];
    const float* bamv = (const float*)d_in[11];
    const float* Wc0  = (const float*)d_in[12];
    const float* bc0  = (const float*)d_in[13];
    const float* Wm1  = (const float*)d_in[14];
    const float* bm1  = (const float*)d_in[15];
    const float* Wz   = (const float*)d_in[16];
    const float* bz   = (const float*)d_in[17];
    const float* Wzmv = (const float*)d_in[18];
    const float* bzmv = (const float*)d_in[19];
    float* out = (float*)d_out;

    cudaFuncSetAttribute(fused_k, cudaFuncAttributeMaxDynamicSharedMemorySize, SMEM_TOTAL);

    // pre-chunk weights (3624 blocks cover 1855488 elements)
    prep_k<<<3624, 512>>>(Wc0, Wm1, Wemv, Wzmv, Wamv, We, Wz, Wza);

    fused_k<<<BB / 128, 512, SMEM_TOTAL>>>(
        control_key, memory_key,
        control_qa, memory_value,
        be, bemv, bza, bamv, bc0, bm1, bz, bzmv,
        out);
}